// round 6
// baseline (speedup 1.0000x reference)
#include <cuda_runtime.h>
#include <math.h>
#include <stdint.h>

#define Bdim 8
#define Sdim 4096
#define Ddim 1024
#define Mdim (Bdim * Sdim)   /* 32768 */
#define Ndim (2 * Ddim)      /* 2048  */
#define NCTA 128             /* scan CTAs, 8 dims each */

/* packed fp32x2 FMA (Blackwell dual-FP32 pipe; PTX-only route) */
#define FMA_F32X2(d, a, b, c) \
    asm("fma.rn.f32x2 %0, %1, %2, %3;" : "=l"(d) : "l"(a), "l"(b), "l"(c))
#define PACK_F2(d, s) \
    asm("mov.b64 %0, {%1, %1};" : "=l"(d) : "f"(s))
#define UNPACK_F2(lo, hi, v) \
    asm("mov.b64 {%0, %1}, %2;" : "=f"(lo), "=f"(hi) : "l"(v))

/* ---------------- scratch (device globals; no allocation allowed) -------- */
__device__ float g_G[(size_t)Mdim * Ddim];       /* gates   [B,S,D] 134 MB */
__device__ float g_P[(size_t)Mdim * Ddim];       /* proj_in [B,S,D] 134 MB */
__device__ float g_state[2][Bdim * Ddim];        /* double-buffered state  */
__device__ unsigned g_bar[32];                   /* [0] used, padded line  */
__device__ volatile unsigned g_epoch[32];        /* [0] used               */

/* ---------------- init: reset state + barrier each run ------------------- */
__global__ void init_kernel() {
    int i = blockIdx.x * blockDim.x + threadIdx.x;
    if (i < 2 * Bdim * Ddim) ((float*)g_state)[i] = 0.0f;
    if (i == 0) { g_bar[0] = 0; g_epoch[0] = 0; }
}

/* ---------------- Phase 1: fused GEMM + bias + sigmoid split ------------- */
/* C[m,n] = sum_k x[m,k] * W_in[n,k] + b_in[n];  n<1024 -> sigmoid -> g_G,
   n>=1024 -> g_P.  128x128 tile, BK=16, 256 thr, 8x8 microtile.
   Register-double-buffered loads + packed f32x2 FMA compute.               */
#define TM 128
#define TN 128
#define TK 16

__global__ __launch_bounds__(256) void gemm_kernel(
    const float* __restrict__ A,    /* x      [32768,1024] */
    const float* __restrict__ Wf,   /* W_in   [2048,1024]  */
    const float* __restrict__ bin)  /* b_in   [2048]       */
{
    __shared__ float As[TK][TM + 4];
    __shared__ float Bs[TK][TN + 4];

    const int n0 = blockIdx.x * TN;
    const int m0 = blockIdx.y * TM;
    const int tid = threadIdx.x;
    const int tx = tid & 15;        /* 0..15 -> 8 cols each */
    const int ty = tid >> 4;        /* 0..15 -> 8 rows each */
    const int lr = tid >> 2;        /* loader row 0..63 (+64) */
    const int lc = (tid & 3) * 4;   /* loader k-offset 0,4,8,12 */

    /* accumulators: 8 rows x 4 packed f32x2 (= 8x8 scalars) */
    uint64_t accp[8][4];
#pragma unroll
    for (int i = 0; i < 8; i++)
#pragma unroll
        for (int j = 0; j < 4; j++) accp[i][j] = 0ULL;

    /* prologue: fetch k-tile 0 into registers */
    float4 pa[2], pb[2];
#pragma unroll
    for (int h = 0; h < 2; h++) {
        int r = lr + h * 64;
        pa[h] = *(const float4*)&A[(size_t)(m0 + r) * Ddim + lc];
        pb[h] = *(const float4*)&Wf[(size_t)(n0 + r) * Ddim + lc];
    }

    for (int kt = 0; kt < Ddim; kt += TK) {
        /* commit prefetched tile to SMEM */
#pragma unroll
        for (int h = 0; h < 2; h++) {
            int r = lr + h * 64;
            As[lc + 0][r] = pa[h].x; As[lc + 1][r] = pa[h].y;
            As[lc + 2][r] = pa[h].z; As[lc + 3][r] = pa[h].w;
            Bs[lc + 0][r] = pb[h].x; Bs[lc + 1][r] = pb[h].y;
            Bs[lc + 2][r] = pb[h].z; Bs[lc + 3][r] = pb[h].w;
        }
        __syncthreads();

        /* prefetch NEXT k-tile while computing on this one */
        if (kt + TK < Ddim) {
#pragma unroll
            for (int h = 0; h < 2; h++) {
                int r = lr + h * 64;
                pa[h] = *(const float4*)&A[(size_t)(m0 + r) * Ddim + kt + TK + lc];
                pb[h] = *(const float4*)&Wf[(size_t)(n0 + r) * Ddim + kt + TK + lc];
            }
        }

#pragma unroll
        for (int kk = 0; kk < TK; kk++) {
            float ra[8];
            *(float4*)&ra[0] = *(const float4*)&As[kk][ty * 8];
            *(float4*)&ra[4] = *(const float4*)&As[kk][ty * 8 + 4];
            ulonglong2 rb0 = *(const ulonglong2*)&Bs[kk][tx * 8];
            ulonglong2 rb1 = *(const ulonglong2*)&Bs[kk][tx * 8 + 4];
            uint64_t rbp0 = rb0.x, rbp1 = rb0.y, rbp2 = rb1.x, rbp3 = rb1.y;
#pragma unroll
            for (int i = 0; i < 8; i++) {
                uint64_t rap;
                PACK_F2(rap, ra[i]);
                FMA_F32X2(accp[i][0], rap, rbp0, accp[i][0]);
                FMA_F32X2(accp[i][1], rap, rbp1, accp[i][1]);
                FMA_F32X2(accp[i][2], rap, rbp2, accp[i][2]);
                FMA_F32X2(accp[i][3], rap, rbp3, accp[i][3]);
            }
        }
        __syncthreads();
    }

    /* epilogue: bias (+ sigmoid for gate half), vector stores */
    const bool is_gate = (n0 < Ddim);
    float* dst = is_gate ? g_G : g_P;
    const int ncol = is_gate ? n0 : (n0 - Ddim);

    float bb[8];
#pragma unroll
    for (int j = 0; j < 8; j++) bb[j] = bin[n0 + tx * 8 + j];

#pragma unroll
    for (int i = 0; i < 8; i++) {
        int m = m0 + ty * 8 + i;
        float v[8];
#pragma unroll
        for (int j = 0; j < 4; j++) {
            float c0, c1;
            UNPACK_F2(c0, c1, accp[i][j]);
            float z0 = c0 + bb[2 * j];
            float z1 = c1 + bb[2 * j + 1];
            v[2 * j]     = is_gate ? (1.0f / (1.0f + expf(-z0))) : z0;
            v[2 * j + 1] = is_gate ? (1.0f / (1.0f + expf(-z1))) : z1;
        }
        float* o = &dst[(size_t)m * Ddim + ncol + tx * 8];
        *(float4*)&o[0] = *(float4*)&v[0];
        *(float4*)&o[4] = *(float4*)&v[4];
    }
}

/* ---------------- Phase 2: persistent grid-synced scan ------------------- */
/* 128 CTAs x 256 threads. CTA c owns output dims [8c, 8c+8).
   SMEM: Wt[1024][8] (W_s slice transposed), Ssh[8][1024] (staged state),
   red[8][8][8] reduction, bsh[8].
   Thread t: b = t&7, c = t>>3 owns k-chunk {c + 32*i}.
   Matvec uses packed f32x2 FMA (4 per iter instead of 8 scalar).           */
#define SCAN_SMEM_FLOATS (8192 + 8192 + 512 + 8)

__global__ __launch_bounds__(256, 1) void scan_kernel(
    const float* __restrict__ Ws,   /* W_s [1024,1024] */
    const float* __restrict__ bsv,  /* b_s [1024]      */
    float* __restrict__ out)        /* [B,S,D]         */
{
    extern __shared__ float sm[];
    float* Wt  = sm;                  /* [k*8 + dd]            */
    float* Ssh = sm + 8192;           /* [b*1024 + k]          */
    float* red = sm + 16384;          /* [w*64 + b*8 + dd]     */
    float* bsh = sm + 16384 + 512;    /* [8]                   */

    const int tid = threadIdx.x;
    const int j0 = blockIdx.x * 8;
    const int b = tid & 7;
    const int c = tid >> 3;           /* 0..31 */
    const int lane = tid & 31;
    const int warp = tid >> 5;
    const int ob = tid >> 3;          /* final-update batch (tid<64)  */
    const int od = tid & 7;           /* final-update dim-in-slice    */

    /* load W_s slice transposed: Wt[k][dd] = Ws[j0+dd][k] (one-time) */
    for (int idx = tid; idx < 8192; idx += 256) {
        int dd = idx >> 10, k = idx & 1023;
        Wt[k * 8 + dd] = Ws[(size_t)(j0 + dd) * Ddim + k];
    }
    if (tid < 8) bsh[tid] = bsv[j0 + tid];
    __syncthreads();

    for (int t = 0; t < Sdim; t++) {
        /* prefetch gate/proj for this step (independent of barrier) */
        float gv = 0.0f, pv = 0.0f;
        size_t gidx = 0;
        if (tid < 64) {
            gidx = ((size_t)ob * Sdim + t) * (size_t)Ddim + j0 + od;
            gv = g_G[gidx];
            pv = g_P[gidx];
        }

        /* wait for epoch == t (all CTAs finished step t-1) */
        if (t > 0) {
            if (tid == 0) {
                while (g_epoch[0] < (unsigned)t) { }
                __threadfence();  /* acquire */
            }
            __syncthreads();
        }

        /* stage state buf[t&1] -> SMEM (coalesced float4) */
        {
            const float4* src = (const float4*)g_state[t & 1];
            float4* dstS = (float4*)Ssh;
#pragma unroll
            for (int h = 0; h < 8; h++) dstS[tid + h * 256] = src[tid + h * 256];
        }
        __syncthreads();

        /* matvec: accp[dd-pair] += state[b][k] * Wt[k][dd], k = c + 32*i */
        uint64_t accp[4] = {0ULL, 0ULL, 0ULL, 0ULL};
        const float* sb = Ssh + b * 1024 + c;
        const float* wb = Wt + c * 8;
#pragma unroll
        for (int i = 0; i < 32; i++) {
            float s = sb[32 * i];
            uint64_t s2;
            PACK_F2(s2, s);
            ulonglong2 w0 = *(const ulonglong2*)&wb[256 * i];
            ulonglong2 w1 = *(const ulonglong2*)&wb[256 * i + 4];
            FMA_F32X2(accp[0], s2, w0.x, accp[0]);
            FMA_F32X2(accp[1], s2, w0.y, accp[1]);
            FMA_F32X2(accp[2], s2, w1.x, accp[2]);
            FMA_F32X2(accp[3], s2, w1.y, accp[3]);
        }
        float acc[8];
#pragma unroll
        for (int j = 0; j < 4; j++) UNPACK_F2(acc[2 * j], acc[2 * j + 1], accp[j]);

        /* reduce over c: 4 chunks within warp (lane bits 3,4), 8 warps via SMEM */
#pragma unroll
        for (int j = 0; j < 8; j++) {
            acc[j] += __shfl_xor_sync(0xffffffffu, acc[j], 8);
            acc[j] += __shfl_xor_sync(0xffffffffu, acc[j], 16);
        }
        if (lane < 8) {
#pragma unroll
            for (int j = 0; j < 8; j++) red[warp * 64 + lane * 8 + j] = acc[j];
        }
        __syncthreads();

        /* final update + emit (64 threads: b=ob, dim=j0+od) */
        if (tid < 64) {
            float tot = 0.0f;
#pragma unroll
            for (int w = 0; w < 8; w++) tot += red[w * 64 + tid];
            float mix = tot + bsh[od] + pv;
            float sold = Ssh[ob * 1024 + j0 + od];
            float ns = fmaf(gv, mix - sold, sold);  /* g*mix + (1-g)*s */
            g_state[(t + 1) & 1][ob * 1024 + j0 + od] = ns;
            out[gidx] = ns;
            __threadfence();  /* release my slice before barrier arrive */
        }
        __syncthreads();

        /* grid barrier arrive: last CTA resets counter and bumps epoch */
        if (tid == 0) {
            unsigned prev = atomicAdd(&g_bar[0], 1u);
            if (prev == NCTA - 1) {
                g_bar[0] = 0;
                __threadfence();
                g_epoch[0] = (unsigned)(t + 1);
            }
        }
    }
}

/* ---------------- launch ------------------------------------------------- */
extern "C" void kernel_launch(void* const* d_in, const int* in_sizes, int n_in,
                              void* d_out, int out_size) {
    const float* x    = (const float*)d_in[0];
    const float* W_in = (const float*)d_in[1];
    const float* b_in = (const float*)d_in[2];
    const float* W_s  = (const float*)d_in[3];
    const float* b_s  = (const float*)d_in[4];
    float* out = (float*)d_out;

    cudaFuncSetAttribute(scan_kernel, cudaFuncAttributeMaxDynamicSharedMemorySize,
                         SCAN_SMEM_FLOATS * (int)sizeof(float));

    init_kernel<<<64, 256>>>();

    dim3 ggrid(Ndim / TN, Mdim / TM);   /* (16, 256) */
    gemm_kernel<<<ggrid, 256>>>(x, W_in, b_in);

    scan_kernel<<<NCTA, 256, SCAN_SMEM_FLOATS * (int)sizeof(float)>>>(W_s, b_s, out);
}